// round 6
// baseline (speedup 1.0000x reference)
#include <cuda_runtime.h>
#include <cuda_bf16.h>
#include <cstdint>

#define HID 2048
#define MLP 8192
#define BATCH 256
#define NELEM_A (BATCH*HID)
#define NELEM_T (BATCH*MLP)
#define SROW 40
#define GEMM_SMEM (2048 + 2*256*SROW*2 + 2*64*SROW*2)

__device__ __align__(16) __nv_bfloat16 g_a_hi[NELEM_A];
__device__ __align__(16) __nv_bfloat16 g_a_lo[NELEM_A];
__device__ __align__(16) __nv_bfloat16 g_t_hi[NELEM_T];
__device__ __align__(16) __nv_bfloat16 g_t_lo[NELEM_T];
__device__ __align__(16) float g_gate[NELEM_T];
__device__ __align__(16) float g_up[NELEM_T];
__device__ __align__(16) float g_part[4*NELEM_A];

__device__ __forceinline__ uint32_t pack_bf2(__nv_bfloat16 a, __nv_bfloat16 b) {
    return (uint32_t)__bfloat16_as_ushort(a) | ((uint32_t)__bfloat16_as_ushort(b) << 16);
}
__device__ __forceinline__ float fp4_decode(int n) {
    int m = n & 7;
    float mag;
    if (m == 0) mag = 0.0f;
    else if (m == 1) mag = 0.5f;
    else mag = (1.0f + 0.5f * (float)(m & 1)) * (float)(1 << ((m >> 1) - 1));
    return (n & 8) ? -mag : mag;
}
__device__ __forceinline__ void dq2(uint32_t w, float s, const float2* __restrict__ lut,
                                    uint32_t& hi, uint32_t& lo) {
    float2 p = lut[w & 255u];
    float f0 = p.x * s, f1 = p.y * s;
    __nv_bfloat16 h0 = __float2bfloat16(f0), h1 = __float2bfloat16(f1);
    hi = pack_bf2(h0, h1);
    lo = pack_bf2(__float2bfloat16(f0 - __bfloat162float(h0)),
                  __float2bfloat16(f1 - __bfloat162float(h1)));
}
__device__ __forceinline__ void mma_bf16(float* c, const uint32_t* a, const uint32_t* b) {
    asm volatile(
        "mma.sync.aligned.m16n8k16.row.col.f32.bf16.bf16.f32 "
        "{%0,%1,%2,%3}, {%4,%5,%6,%7}, {%8,%9}, {%0,%1,%2,%3};\n"
        : "+f"(c[0]), "+f"(c[1]), "+f"(c[2]), "+f"(c[3])
        : "r"(a[0]), "r"(a[1]), "r"(a[2]), "r"(a[3]), "r"(b[0]), "r"(b[1]));
}

// Generic GEMM: out[b, n] (+split offset) = A[b, :] . W[n, :], NVFP4 W dequant on the fly.
// CTA tile 256x64, BK=32, grid (N/64, nsplit). K = full K (strides); each split does 64 k-tiles.
__global__ void __launch_bounds__(512) gemm_kernel(
    const int* __restrict__ wp_base, const float* __restrict__ ws_base,
    const __nv_bfloat16* __restrict__ a_hi, const __nv_bfloat16* __restrict__ a_lo,
    float* __restrict__ out, int K, int ldN)
{
    extern __shared__ char smem[];
    float2* lut = (float2*)smem;
    __nv_bfloat16* sAh = (__nv_bfloat16*)(smem + 2048);
    __nv_bfloat16* sAl = sAh + 256*SROW;
    __nv_bfloat16* sWh = sAl + 256*SROW;
    __nv_bfloat16* sWl = sWh + 64*SROW;

    const int tid = threadIdx.x;
    const int n0 = blockIdx.x * 64;
    const int kb = blockIdx.y * 64;       // base k-tile of this split
    if (tid < 256) lut[tid] = make_float2(fp4_decode(tid & 15), fp4_decode(tid >> 4));

    const int ar = tid >> 2, aq = tid & 3;
    const __nv_bfloat16* gAh = a_hi + (size_t)ar*K + kb*32 + aq*8;
    const __nv_bfloat16* gAl = a_lo + (size_t)ar*K + kb*32 + aq*8;

    const bool wact = tid < 256;
    const int wn = (tid & 255) >> 2, wc = tid & 3;
    const int* wp = wp_base + (size_t)(n0 + wn)*(K >> 1) + kb*16 + wc*4;
    const float* wsp = ws_base + (size_t)(n0 + wn)*(K >> 5) + kb;

    const int warp = tid >> 5, lane = tid & 31;
    const int wm = warp >> 1, wnw = warp & 1;
    const int g = lane >> 2, tt = lane & 3;

    float acc[32];
#pragma unroll
    for (int i = 0; i < 32; ++i) acc[i] = 0.f;

    uint4 rA0 = *(const uint4*)gAh;
    uint4 rA1 = *(const uint4*)(gAh + (size_t)128*K);
    uint4 rL0 = *(const uint4*)gAl;
    uint4 rL1 = *(const uint4*)(gAl + (size_t)128*K);
    int4  rW  = wact ? *(const int4*)wp : make_int4(0,0,0,0);
    float rS  = wact ? wsp[0] : 0.f;

    for (int it = 0; it < 64; ++it) {
        __syncthreads();
        *(uint4*)(sAh + ar*SROW + aq*8) = rA0;
        *(uint4*)(sAh + (ar+128)*SROW + aq*8) = rA1;
        *(uint4*)(sAl + ar*SROW + aq*8) = rL0;
        *(uint4*)(sAl + (ar+128)*SROW + aq*8) = rL1;
        if (wact) {
            uint32_t h0,h1,h2,h3,l0,l1,l2,l3;
            dq2((uint32_t)rW.x, rS, lut, h0, l0);
            dq2((uint32_t)rW.y, rS, lut, h1, l1);
            dq2((uint32_t)rW.z, rS, lut, h2, l2);
            dq2((uint32_t)rW.w, rS, lut, h3, l3);
            *(uint4*)(sWh + wn*SROW + wc*8) = make_uint4(h0,h1,h2,h3);
            *(uint4*)(sWl + wn*SROW + wc*8) = make_uint4(l0,l1,l2,l3);
        }
        __syncthreads();
        if (it < 63) {
            int off = (it + 1) * 32;
            rA0 = *(const uint4*)(gAh + off);
            rA1 = *(const uint4*)(gAh + (size_t)128*K + off);
            rL0 = *(const uint4*)(gAl + off);
            rL1 = *(const uint4*)(gAl + (size_t)128*K + off);
            if (wact) { rW = *(const int4*)(wp + (it+1)*16); rS = wsp[it+1]; }
        }
#pragma unroll
        for (int ks = 0; ks < 2; ++ks) {
            const int cb = ks*16 + 2*tt;
            uint32_t ah[2][4], al[2][4];
#pragma unroll
            for (int mi = 0; mi < 2; ++mi) {
                const __nv_bfloat16* p = sAh + (wm*32 + mi*16 + g)*SROW + cb;
                ah[mi][0] = *(const uint32_t*)p;
                ah[mi][1] = *(const uint32_t*)(p + 8*SROW);
                ah[mi][2] = *(const uint32_t*)(p + 8);
                ah[mi][3] = *(const uint32_t*)(p + 8*SROW + 8);
                const __nv_bfloat16* q = sAl + (wm*32 + mi*16 + g)*SROW + cb;
                al[mi][0] = *(const uint32_t*)q;
                al[mi][1] = *(const uint32_t*)(q + 8*SROW);
                al[mi][2] = *(const uint32_t*)(q + 8);
                al[mi][3] = *(const uint32_t*)(q + 8*SROW + 8);
            }
#pragma unroll
            for (int ni = 0; ni < 4; ++ni) {
                const int nr = (wnw*32 + ni*8 + g)*SROW + cb;
                uint32_t bh[2] = {*(const uint32_t*)(sWh + nr), *(const uint32_t*)(sWh + nr + 8)};
                uint32_t bl[2] = {*(const uint32_t*)(sWl + nr), *(const uint32_t*)(sWl + nr + 8)};
#pragma unroll
                for (int mi = 0; mi < 2; ++mi) {
                    float* c = acc + mi*16 + ni*4;
                    mma_bf16(c, ah[mi], bh);   // Ah*Wh
                    mma_bf16(c, al[mi], bh);   // Al*Wh
                    mma_bf16(c, ah[mi], bl);   // Ah*Wl
                }
            }
        }
    }

    float* po = out + (size_t)blockIdx.y * BATCH * ldN;
#pragma unroll
    for (int mi = 0; mi < 2; ++mi)
#pragma unroll
        for (int ni = 0; ni < 4; ++ni) {
            const float* c = acc + mi*16 + ni*4;
            int r0 = wm*32 + mi*16 + g;
            int j = n0 + wnw*32 + ni*8 + 2*tt;
            *(float2*)(po + (size_t)r0*ldN + j)     = make_float2(c[0], c[1]);
            *(float2*)(po + (size_t)(r0+8)*ldN + j) = make_float2(c[2], c[3]);
        }
}

__global__ void split_x_kernel(const float* __restrict__ x) {
    int i = blockIdx.x * 256 + threadIdx.x;
    float v = x[i];
    __nv_bfloat16 h = __float2bfloat16(v);
    g_a_hi[i] = h;
    g_a_lo[i] = __float2bfloat16(v - __bfloat162float(h));
}

__global__ void silu_mul_split_kernel() {
    int i = blockIdx.x * 256 + threadIdx.x;
    float gg = g_gate[i];
    float t = (gg / (1.0f + __expf(-gg))) * g_up[i];
    __nv_bfloat16 h = __float2bfloat16(t);
    g_t_hi[i] = h;
    g_t_lo[i] = __float2bfloat16(t - __bfloat162float(h));
}

__global__ void reduce_split_kernel(float* __restrict__ out, int final_layer) {
    int i = blockIdx.x * 256 + threadIdx.x;
    float s = g_part[i] + g_part[i + NELEM_A] + g_part[i + 2*NELEM_A] + g_part[i + 3*NELEM_A];
    if (final_layer) {
        out[i] = s;
    } else {
        __nv_bfloat16 h = __float2bfloat16(s);
        g_a_hi[i] = h;
        g_a_lo[i] = __float2bfloat16(s - __bfloat162float(h));
    }
}

extern "C" void kernel_launch(void* const* d_in, const int* in_sizes, int n_in,
                              void* d_out, int out_size) {
    const float* x  = (const float*)d_in[0];
    const int*   gp = (const int*)d_in[1];
    const float* gs = (const float*)d_in[2];
    const int*   up = (const int*)d_in[3];
    const float* us = (const float*)d_in[4];
    const int*   dp = (const int*)d_in[5];
    const float* ds = (const float*)d_in[6];
    float* out = (float*)d_out;

    cudaFuncSetAttribute(gemm_kernel, cudaFuncAttributeMaxDynamicSharedMemorySize, GEMM_SMEM);

    void *p_ah, *p_al, *p_th, *p_tl, *p_g, *p_u, *p_part;
    cudaGetSymbolAddress(&p_ah, g_a_hi);
    cudaGetSymbolAddress(&p_al, g_a_lo);
    cudaGetSymbolAddress(&p_th, g_t_hi);
    cudaGetSymbolAddress(&p_tl, g_t_lo);
    cudaGetSymbolAddress(&p_g, g_gate);
    cudaGetSymbolAddress(&p_u, g_up);
    cudaGetSymbolAddress(&p_part, g_part);

    split_x_kernel<<<NELEM_A/256, 256>>>(x);

    for (int l = 0; l < 18; ++l) {
        const size_t woff = (size_t)l * MLP * (HID/2);   // gate/up packed per layer
        const size_t soff = (size_t)l * MLP * (HID/32);  // gate/up scales per layer
        const size_t dwoff = (size_t)l * HID * (MLP/2);
        const size_t dsoff = (size_t)l * HID * (MLP/32);

        gemm_kernel<<<dim3(MLP/64, 1), 512, GEMM_SMEM>>>(
            gp + woff, gs + soff,
            (const __nv_bfloat16*)p_ah, (const __nv_bfloat16*)p_al,
            (float*)p_g, HID, MLP);
        gemm_kernel<<<dim3(MLP/64, 1), 512, GEMM_SMEM>>>(
            up + woff, us + soff,
            (const __nv_bfloat16*)p_ah, (const __nv_bfloat16*)p_al,
            (float*)p_u, HID, MLP);
        silu_mul_split_kernel<<<NELEM_T/256, 256>>>();
        gemm_kernel<<<dim3(HID/64, 4), 512, GEMM_SMEM>>>(
            dp + dwoff, ds + dsoff,
            (const __nv_bfloat16*)p_th, (const __nv_bfloat16*)p_tl,
            (float*)p_part, MLP, HID);
        reduce_split_kernel<<<NELEM_A/256, 256>>>(out, l == 17 ? 1 : 0);
    }
}

// round 7
// speedup vs baseline: 1.0301x; 1.0301x over previous
#include <cuda_runtime.h>
#include <cuda_bf16.h>
#include <cstdint>

#define HID 2048
#define MLP 8192
#define BATCH 256
#define NELEM_A (BATCH*HID)
#define NELEM_T (BATCH*MLP)
#define SROW 40
// stage = Ah(256*SROW) + Al + Wh(64*SROW) + Wl   (elements)
#define A_LO_OFF (256*SROW)
#define W_HI_OFF (2*256*SROW)
#define W_LO_OFF (2*256*SROW + 64*SROW)
#define STAGE_ELEMS (2*256*SROW + 2*64*SROW)
#define GEMM_SMEM (2048 + 2*STAGE_ELEMS*2)

__device__ __align__(16) __nv_bfloat16 g_a_hi[NELEM_A];
__device__ __align__(16) __nv_bfloat16 g_a_lo[NELEM_A];
__device__ __align__(16) __nv_bfloat16 g_t_hi[NELEM_T];
__device__ __align__(16) __nv_bfloat16 g_t_lo[NELEM_T];
__device__ __align__(16) float g_gate[NELEM_T];
__device__ __align__(16) float g_part[4*NELEM_A];

__device__ __forceinline__ uint32_t pack_bf2(__nv_bfloat16 a, __nv_bfloat16 b) {
    return (uint32_t)__bfloat16_as_ushort(a) | ((uint32_t)__bfloat16_as_ushort(b) << 16);
}
__device__ __forceinline__ float fp4_decode(int n) {
    int m = n & 7;
    float mag;
    if (m == 0) mag = 0.0f;
    else if (m == 1) mag = 0.5f;
    else mag = (1.0f + 0.5f * (float)(m & 1)) * (float)(1 << ((m >> 1) - 1));
    return (n & 8) ? -mag : mag;
}
__device__ __forceinline__ float silu_f(float v) {
    return v / (1.0f + __expf(-v));
}
__device__ __forceinline__ void dq2(uint32_t w, float s, const float2* __restrict__ lut,
                                    uint32_t& hi, uint32_t& lo) {
    float2 p = lut[w & 255u];
    float f0 = p.x * s, f1 = p.y * s;
    __nv_bfloat16 h0 = __float2bfloat16(f0), h1 = __float2bfloat16(f1);
    hi = pack_bf2(h0, h1);
    lo = pack_bf2(__float2bfloat16(f0 - __bfloat162float(h0)),
                  __float2bfloat16(f1 - __bfloat162float(h1)));
}
__device__ __forceinline__ void mma_bf16(float* c, const uint32_t* a, const uint32_t* b) {
    asm volatile(
        "mma.sync.aligned.m16n8k16.row.col.f32.bf16.bf16.f32 "
        "{%0,%1,%2,%3}, {%4,%5,%6,%7}, {%8,%9}, {%0,%1,%2,%3};\n"
        : "+f"(c[0]), "+f"(c[1]), "+f"(c[2]), "+f"(c[3])
        : "r"(a[0]), "r"(a[1]), "r"(a[2]), "r"(a[3]), "r"(b[0]), "r"(b[1]));
}
__device__ __forceinline__ void ldsm4(uint32_t* r, uint32_t addr) {
    asm volatile("ldmatrix.sync.aligned.m8n8.x4.shared.b16 {%0,%1,%2,%3}, [%4];"
                 : "=r"(r[0]), "=r"(r[1]), "=r"(r[2]), "=r"(r[3]) : "r"(addr));
}

// Generic GEMM, CTA tile 256x64, BK=32, 64 k-tiles per CTA. grid (N/64, nsplit).
// mode 0: out fp32 [+ blockIdx.y*BATCH*ldN]   (gate GEMM, down GEMM partials)
// mode 1: t = silu(gatebuf) * acc -> bf16 hi/lo split into t_hi/t_lo (up GEMM)
__global__ void __launch_bounds__(512) gemm_kernel(
    const int* __restrict__ wp_base, const float* __restrict__ ws_base,
    const __nv_bfloat16* __restrict__ a_hi, const __nv_bfloat16* __restrict__ a_lo,
    float* __restrict__ out, int K, int ldN, int mode,
    const float* __restrict__ gatebuf,
    __nv_bfloat16* __restrict__ t_hi, __nv_bfloat16* __restrict__ t_lo)
{
    extern __shared__ char smem[];
    float2* lut = (float2*)smem;
    __nv_bfloat16* st[2];
    st[0] = (__nv_bfloat16*)(smem + 2048);
    st[1] = st[0] + STAGE_ELEMS;
    uint32_t ub[2];
    ub[0] = (uint32_t)__cvta_generic_to_shared(st[0]);
    ub[1] = (uint32_t)__cvta_generic_to_shared(st[1]);

    const int tid = threadIdx.x;
    const int n0 = blockIdx.x * 64;
    const int kb = blockIdx.y * 64;
    if (tid < 256) lut[tid] = make_float2(fp4_decode(tid & 15), fp4_decode(tid >> 4));

    const int ar = tid >> 2, aq = tid & 3;
    const __nv_bfloat16* gAh = a_hi + (size_t)ar*K + kb*32 + aq*8;
    const __nv_bfloat16* gAl = a_lo + (size_t)ar*K + kb*32 + aq*8;

    const bool wact = tid < 256;
    const int wn = (tid & 255) >> 2, wc = tid & 3;
    const int* wp = wp_base + (size_t)(n0 + wn)*(K >> 1) + kb*16 + wc*4;
    const float* wsp = ws_base + (size_t)(n0 + wn)*(K >> 5) + kb;

    const int warp = tid >> 5, lane = tid & 31;
    const int wm = warp >> 1, wnw = warp & 1;
    const int g = lane >> 2, tt = lane & 3;

    // per-lane ldmatrix byte offsets (relative to tile origin)
    const uint32_t a_off = (uint32_t)(((wm*32 + (lane & 15))*SROW + (lane >> 4)*8) * 2);
    const uint32_t b_off = (uint32_t)(((wnw*32 + ((lane >> 4) << 3) + (lane & 7))*SROW
                                      + ((lane >> 3) & 1)*8) * 2);

    float acc[32];
#pragma unroll
    for (int i = 0; i < 32; ++i) acc[i] = 0.f;

    // ---- prologue: load tile 0, stage into buffer 0 ----
    uint4 rA0 = *(const uint4*)gAh;
    uint4 rA1 = *(const uint4*)(gAh + (size_t)128*K);
    uint4 rL0 = *(const uint4*)gAl;
    uint4 rL1 = *(const uint4*)(gAl + (size_t)128*K);
    int4  rW  = wact ? *(const int4*)wp : make_int4(0,0,0,0);
    float rS  = wact ? wsp[0] : 0.f;
    __syncthreads();   // lut ready before any dq
    {
        __nv_bfloat16* s = st[0];
        *(uint4*)(s + ar*SROW + aq*8) = rA0;
        *(uint4*)(s + (ar+128)*SROW + aq*8) = rA1;
        *(uint4*)(s + A_LO_OFF + ar*SROW + aq*8) = rL0;
        *(uint4*)(s + A_LO_OFF + (ar+128)*SROW + aq*8) = rL1;
        if (wact) {
            uint32_t h0,h1,h2,h3,l0,l1,l2,l3;
            dq2((uint32_t)rW.x, rS, lut, h0, l0);
            dq2((uint32_t)rW.y, rS, lut, h1, l1);
            dq2((uint32_t)rW.z, rS, lut, h2, l2);
            dq2((uint32_t)rW.w, rS, lut, h3, l3);
            *(uint4*)(s + W_HI_OFF + wn*SROW + wc*8) = make_uint4(h0,h1,h2,h3);
            *(uint4*)(s + W_LO_OFF + wn*SROW + wc*8) = make_uint4(l0,l1,l2,l3);
        }
    }
    __syncthreads();

    for (int it = 0; it < 64; ++it) {
        const bool pf = it < 63;
        if (pf) {
            int off = (it + 1) * 32;
            rA0 = *(const uint4*)(gAh + off);
            rA1 = *(const uint4*)(gAh + (size_t)128*K + off);
            rL0 = *(const uint4*)(gAl + off);
            rL1 = *(const uint4*)(gAl + (size_t)128*K + off);
            if (wact) { rW = *(const int4*)(wp + (it+1)*16); rS = wsp[it+1]; }
        }
        const uint32_t u = ub[it & 1];
#pragma unroll
        for (int ks = 0; ks < 2; ++ks) {
            const uint32_t kso = (uint32_t)(ks*16*2);
            uint32_t ah[2][4], al[2][4];
#pragma unroll
            for (int mi = 0; mi < 2; ++mi) {
                const uint32_t mo = (uint32_t)(mi*16*SROW*2);
                ldsm4(ah[mi], u + a_off + mo + kso);
                ldsm4(al[mi], u + (uint32_t)(A_LO_OFF*2) + a_off + mo + kso);
            }
            uint32_t bh[2][4], bl[2][4];
#pragma unroll
            for (int gb = 0; gb < 2; ++gb) {
                const uint32_t go = (uint32_t)(gb*16*SROW*2);
                ldsm4(bh[gb], u + (uint32_t)(W_HI_OFF*2) + b_off + go + kso);
                ldsm4(bl[gb], u + (uint32_t)(W_LO_OFF*2) + b_off + go + kso);
            }
#pragma unroll
            for (int ni = 0; ni < 4; ++ni) {
                const uint32_t* ph = &bh[ni >> 1][(ni & 1)*2];
                const uint32_t* pl = &bl[ni >> 1][(ni & 1)*2];
#pragma unroll
                for (int mi = 0; mi < 2; ++mi) {
                    float* c = acc + mi*16 + ni*4;
                    mma_bf16(c, ah[mi], ph);   // Ah*Wh
                    mma_bf16(c, al[mi], ph);   // Al*Wh
                    mma_bf16(c, ah[mi], pl);   // Ah*Wl
                }
            }
        }
        if (pf) {
            __nv_bfloat16* s = st[(it + 1) & 1];
            *(uint4*)(s + ar*SROW + aq*8) = rA0;
            *(uint4*)(s + (ar+128)*SROW + aq*8) = rA1;
            *(uint4*)(s + A_LO_OFF + ar*SROW + aq*8) = rL0;
            *(uint4*)(s + A_LO_OFF + (ar+128)*SROW + aq*8) = rL1;
            if (wact) {
                uint32_t h0,h1,h2,h3,l0,l1,l2,l3;
                dq2((uint32_t)rW.x, rS, lut, h0, l0);
                dq2((uint32_t)rW.y, rS, lut, h1, l1);
                dq2((uint32_t)rW.z, rS, lut, h2, l2);
                dq2((uint32_t)rW.w, rS, lut, h3, l3);
                *(uint4*)(s + W_HI_OFF + wn*SROW + wc*8) = make_uint4(h0,h1,h2,h3);
                *(uint4*)(s + W_LO_OFF + wn*SROW + wc*8) = make_uint4(l0,l1,l2,l3);
            }
            __syncthreads();
        }
    }

    if (mode == 1) {
        // t = silu(gate) * acc -> bf16 hi/lo split
#pragma unroll
        for (int mi = 0; mi < 2; ++mi)
#pragma unroll
            for (int ni = 0; ni < 4; ++ni) {
                const float* c = acc + mi*16 + ni*4;
                int r0 = wm*32 + mi*16 + g;
                int j = n0 + wnw*32 + ni*8 + 2*tt;
                {
                    float t0 = silu_f(gatebuf[(size_t)r0*ldN + j])     * c[0];
                    float t1 = silu_f(gatebuf[(size_t)r0*ldN + j + 1]) * c[1];
                    __nv_bfloat16 h0 = __float2bfloat16(t0), h1 = __float2bfloat16(t1);
                    *(uint32_t*)(t_hi + (size_t)r0*ldN + j) = pack_bf2(h0, h1);
                    *(uint32_t*)(t_lo + (size_t)r0*ldN + j) =
                        pack_bf2(__float2bfloat16(t0 - __bfloat162float(h0)),
                                 __float2bfloat16(t1 - __bfloat162float(h1)));
                }
                {
                    int r1 = r0 + 8;
                    float t2 = silu_f(gatebuf[(size_t)r1*ldN + j])     * c[2];
                    float t3 = silu_f(gatebuf[(size_t)r1*ldN + j + 1]) * c[3];
                    __nv_bfloat16 h2 = __float2bfloat16(t2), h3 = __float2bfloat16(t3);
                    *(uint32_t*)(t_hi + (size_t)r1*ldN + j) = pack_bf2(h2, h3);
                    *(uint32_t*)(t_lo + (size_t)r1*ldN + j) =
                        pack_bf2(__float2bfloat16(t2 - __bfloat162float(h2)),
                                 __float2bfloat16(t3 - __bfloat162float(h3)));
                }
            }
    } else {
        float* po = out + (size_t)blockIdx.y * BATCH * ldN;
#pragma unroll
        for (int mi = 0; mi < 2; ++mi)
#pragma unroll
            for (int ni = 0; ni < 4; ++ni) {
                const float* c = acc + mi*16 + ni*4;
                int r0 = wm*32 + mi*16 + g;
                int j = n0 + wnw*32 + ni*8 + 2*tt;
                *(float2*)(po + (size_t)r0*ldN + j)     = make_float2(c[0], c[1]);
                *(float2*)(po + (size_t)(r0+8)*ldN + j) = make_float2(c[2], c[3]);
            }
    }
}

__global__ void split_x_kernel(const float* __restrict__ x) {
    int i = blockIdx.x * 256 + threadIdx.x;
    float v = x[i];
    __nv_bfloat16 h = __float2bfloat16(v);
    g_a_hi[i] = h;
    g_a_lo[i] = __float2bfloat16(v - __bfloat162float(h));
}

__global__ void reduce_split_kernel(float* __restrict__ out, int final_layer) {
    int i = blockIdx.x * 256 + threadIdx.x;
    float s = g_part[i] + g_part[i + NELEM_A] + g_part[i + 2*NELEM_A] + g_part[i + 3*NELEM_A];
    if (final_layer) {
        out[i] = s;
    } else {
        __nv_bfloat16 h = __float2bfloat16(s);
        g_a_hi[i] = h;
        g_a_lo[i] = __float2bfloat16(s - __bfloat162float(h));
    }
}

extern "C" void kernel_launch(void* const* d_in, const int* in_sizes, int n_in,
                              void* d_out, int out_size) {
    const float* x  = (const float*)d_in[0];
    const int*   gp = (const int*)d_in[1];
    const float* gs = (const float*)d_in[2];
    const int*   up = (const int*)d_in[3];
    const float* us = (const float*)d_in[4];
    const int*   dp = (const int*)d_in[5];
    const float* ds = (const float*)d_in[6];
    float* out = (float*)d_out;

    cudaFuncSetAttribute(gemm_kernel, cudaFuncAttributeMaxDynamicSharedMemorySize, GEMM_SMEM);

    void *p_ah, *p_al, *p_th, *p_tl, *p_g, *p_part;
    cudaGetSymbolAddress(&p_ah, g_a_hi);
    cudaGetSymbolAddress(&p_al, g_a_lo);
    cudaGetSymbolAddress(&p_th, g_t_hi);
    cudaGetSymbolAddress(&p_tl, g_t_lo);
    cudaGetSymbolAddress(&p_g, g_gate);
    cudaGetSymbolAddress(&p_part, g_part);

    split_x_kernel<<<NELEM_A/256, 256>>>(x);

    for (int l = 0; l < 18; ++l) {
        const size_t woff = (size_t)l * MLP * (HID/2);
        const size_t soff = (size_t)l * MLP * (HID/32);
        const size_t dwoff = (size_t)l * HID * (MLP/2);
        const size_t dsoff = (size_t)l * HID * (MLP/32);

        // gate -> g_gate (fp32)
        gemm_kernel<<<dim3(MLP/64, 1), 512, GEMM_SMEM>>>(
            gp + woff, gs + soff,
            (const __nv_bfloat16*)p_ah, (const __nv_bfloat16*)p_al,
            (float*)p_g, HID, MLP, 0, nullptr, nullptr, nullptr);
        // up, fused silu(gate)*up -> t_hi/t_lo
        gemm_kernel<<<dim3(MLP/64, 1), 512, GEMM_SMEM>>>(
            up + woff, us + soff,
            (const __nv_bfloat16*)p_ah, (const __nv_bfloat16*)p_al,
            nullptr, HID, MLP, 1, (const float*)p_g,
            (__nv_bfloat16*)p_th, (__nv_bfloat16*)p_tl);
        // down, split-K 4 -> partials
        gemm_kernel<<<dim3(HID/64, 4), 512, GEMM_SMEM>>>(
            dp + dwoff, ds + dsoff,
            (const __nv_bfloat16*)p_th, (const __nv_bfloat16*)p_tl,
            (float*)p_part, MLP, HID, 0, nullptr, nullptr, nullptr);
        reduce_split_kernel<<<NELEM_A/256, 256>>>(out, l == 17 ? 1 : 0);
    }
}

// round 9
// speedup vs baseline: 1.0357x; 1.0054x over previous
#include <cuda_runtime.h>
#include <cuda_bf16.h>
#include <cstdint>

#define HID 2048
#define MLP 8192
#define BATCH 256
#define NELEM_A (BATCH*HID)
#define NELEM_T (BATCH*MLP)
#define SROW 40
// stage layout (elements): Ah(128*SROW) | Al | Wh(64*SROW) | Wl
#define A_LO_OFF (128*SROW)
#define W_HI_OFF (2*128*SROW)
#define W_LO_OFF (2*128*SROW + 64*SROW)
#define STAGE_ELEMS (2*128*SROW + 2*64*SROW)
#define GEMM_SMEM (2048 + 2*STAGE_ELEMS*2)

__device__ __align__(16) __nv_bfloat16 g_a_hi[NELEM_A];
__device__ __align__(16) __nv_bfloat16 g_a_lo[NELEM_A];
__device__ __align__(16) __nv_bfloat16 g_t_hi[NELEM_T];
__device__ __align__(16) __nv_bfloat16 g_t_lo[NELEM_T];
__device__ __align__(16) float g_gate[NELEM_T];
__device__ __align__(16) float g_part[4*NELEM_A];

__device__ __forceinline__ uint32_t pack_bf2(__nv_bfloat16 a, __nv_bfloat16 b) {
    return (uint32_t)__bfloat16_as_ushort(a) | ((uint32_t)__bfloat16_as_ushort(b) << 16);
}
__device__ __forceinline__ float fp4_decode(int n) {
    int m = n & 7;
    float mag;
    if (m == 0) mag = 0.0f;
    else if (m == 1) mag = 0.5f;
    else mag = (1.0f + 0.5f * (float)(m & 1)) * (float)(1 << ((m >> 1) - 1));
    return (n & 8) ? -mag : mag;
}
__device__ __forceinline__ float silu_f(float v) { return v / (1.0f + __expf(-v)); }
__device__ __forceinline__ void dq2(uint32_t w, float s, const float2* __restrict__ lut,
                                    uint32_t& hi, uint32_t& lo) {
    float2 p = lut[w & 255u];
    float f0 = p.x * s, f1 = p.y * s;
    __nv_bfloat16 h0 = __float2bfloat16(f0), h1 = __float2bfloat16(f1);
    hi = pack_bf2(h0, h1);
    lo = pack_bf2(__float2bfloat16(f0 - __bfloat162float(h0)),
                  __float2bfloat16(f1 - __bfloat162float(h1)));
}
__device__ __forceinline__ void mma_bf16(float* c, const uint32_t* a, const uint32_t* b) {
    asm volatile(
        "mma.sync.aligned.m16n8k16.row.col.f32.bf16.bf16.f32 "
        "{%0,%1,%2,%3}, {%4,%5,%6,%7}, {%8,%9}, {%0,%1,%2,%3};\n"
        : "+f"(c[0]), "+f"(c[1]), "+f"(c[2]), "+f"(c[3])
        : "r"(a[0]), "r"(a[1]), "r"(a[2]), "r"(a[3]), "r"(b[0]), "r"(b[1]));
}
__device__ __forceinline__ void ldsm4(uint32_t* r, uint32_t addr) {
    asm volatile("ldmatrix.sync.aligned.m8n8.x4.shared.b16 {%0,%1,%2,%3}, [%4];"
                 : "=r"(r[0]), "=r"(r[1]), "=r"(r[2]), "=r"(r[3]) : "r"(addr));
}

// GEMM: CTA tile 128(M) x 64(N), BK=32. grid (N/64, M/128, nsplit). 256 threads, 2 CTAs/SM.
// mode 0: fp32 out (+ blockIdx.z*BATCH*ldN)
// mode 1: t = silu(gatebuf) * acc -> bf16 hi/lo split (up GEMM)
__global__ void __launch_bounds__(256, 2) gemm_kernel(
    const int* __restrict__ wp_base, const float* __restrict__ ws_base,
    const __nv_bfloat16* __restrict__ a_hi, const __nv_bfloat16* __restrict__ a_lo,
    float* __restrict__ out, int Ktot, int ldN, int mode,
    const float* __restrict__ gatebuf,
    __nv_bfloat16* __restrict__ t_hi, __nv_bfloat16* __restrict__ t_lo)
{
    extern __shared__ char smem[];
    float2* lut = (float2*)smem;
    __nv_bfloat16* st[2];
    st[0] = (__nv_bfloat16*)(smem + 2048);
    st[1] = st[0] + STAGE_ELEMS;
    uint32_t ub[2];
    ub[0] = (uint32_t)__cvta_generic_to_shared(st[0]);
    ub[1] = (uint32_t)__cvta_generic_to_shared(st[1]);

    const int tid = threadIdx.x;
    const int n0 = blockIdx.x * 64;
    const int m0 = blockIdx.y * 128;
    const int klen = Ktot / gridDim.z;
    const int kb = blockIdx.z * klen;
    const int nt = klen >> 5;           // k-tiles of 32 (= 64 for all configs)
    lut[tid] = make_float2(fp4_decode(tid & 15), fp4_decode(tid >> 4));

    // A staging map: row ar (0..127), 16-elem half aq
    const int ar = tid >> 1, aq = tid & 1;
    const __nv_bfloat16* gAh = a_hi + (size_t)(m0 + ar) * Ktot + kb + aq * 16;
    const __nv_bfloat16* gAl = a_lo + (size_t)(m0 + ar) * Ktot + kb + aq * 16;
    // W staging map: row wn (0..63), int4 chunk wc (0..3) = 8 values
    const int wn = tid >> 2, wc = tid & 3;
    const int* wp = wp_base + (size_t)(n0 + wn) * (Ktot >> 1) + (kb >> 1) + wc * 4;
    const float* wsp = ws_base + (size_t)(n0 + wn) * (Ktot >> 5) + (kb >> 5);

    const int warp = tid >> 5, lane = tid & 31;
    const int wm = warp >> 1, wnw = warp & 1;   // wm 0..3, wnw 0..1
    const int g = lane >> 2, tt = lane & 3;

    const uint32_t a_off = (uint32_t)(((wm*32 + (lane & 15))*SROW + (lane >> 4)*8) * 2);
    const uint32_t b_off = (uint32_t)(((wnw*32 + ((lane >> 4) << 3) + (lane & 7))*SROW
                                      + ((lane >> 3) & 1)*8) * 2);

    float acc[32];
#pragma unroll
    for (int i = 0; i < 32; ++i) acc[i] = 0.f;

    // ---- prologue: tile 0 into buffer 0 ----
    uint4 rA0 = *(const uint4*)gAh;
    uint4 rA1 = *(const uint4*)(gAh + 8);
    uint4 rL0 = *(const uint4*)gAl;
    uint4 rL1 = *(const uint4*)(gAl + 8);
    int4  rW  = *(const int4*)wp;
    float rS  = wsp[0];
    __syncthreads();   // lut visible
    {
        __nv_bfloat16* s = st[0];
        *(uint4*)(s + ar*SROW + aq*16) = rA0;
        *(uint4*)(s + ar*SROW + aq*16 + 8) = rA1;
        *(uint4*)(s + A_LO_OFF + ar*SROW + aq*16) = rL0;
        *(uint4*)(s + A_LO_OFF + ar*SROW + aq*16 + 8) = rL1;
        uint32_t h0,h1,h2,h3,l0,l1,l2,l3;
        dq2((uint32_t)rW.x, rS, lut, h0, l0);
        dq2((uint32_t)rW.y, rS, lut, h1, l1);
        dq2((uint32_t)rW.z, rS, lut, h2, l2);
        dq2((uint32_t)rW.w, rS, lut, h3, l3);
        *(uint4*)(s + W_HI_OFF + wn*SROW + wc*8) = make_uint4(h0,h1,h2,h3);
        *(uint4*)(s + W_LO_OFF + wn*SROW + wc*8) = make_uint4(l0,l1,l2,l3);
    }
    __syncthreads();

    for (int it = 0; it < nt; ++it) {
        const bool pf = it < nt - 1;
        if (pf) {
            int off = (it + 1) * 32;
            rA0 = *(const uint4*)(gAh + off);
            rA1 = *(const uint4*)(gAh + off + 8);
            rL0 = *(const uint4*)(gAl + off);
            rL1 = *(const uint4*)(gAl + off + 8);
            rW  = *(const int4*)(wp + (it + 1) * 16);
            rS  = wsp[it + 1];
        }
        const uint32_t u = ub[it & 1];
#pragma unroll
        for (int ks = 0; ks < 2; ++ks) {
            const uint32_t kso = (uint32_t)(ks*16*2);
            uint32_t ah[2][4], al[2][4];
#pragma unroll
            for (int mi = 0; mi < 2; ++mi) {
                const uint32_t mo = (uint32_t)(mi*16*SROW*2);
                ldsm4(ah[mi], u + a_off + mo + kso);
                ldsm4(al[mi], u + (uint32_t)(A_LO_OFF*2) + a_off + mo + kso);
            }
            uint32_t bh[2][4], bl[2][4];
#pragma unroll
            for (int gb = 0; gb < 2; ++gb) {
                const uint32_t go = (uint32_t)(gb*16*SROW*2);
                ldsm4(bh[gb], u + (uint32_t)(W_HI_OFF*2) + b_off + go + kso);
                ldsm4(bl[gb], u + (uint32_t)(W_LO_OFF*2) + b_off + go + kso);
            }
#pragma unroll
            for (int ni = 0; ni < 4; ++ni) {
                const uint32_t* ph = &bh[ni >> 1][(ni & 1)*2];
                const uint32_t* pl = &bl[ni >> 1][(ni & 1)*2];
#pragma unroll
                for (int mi = 0; mi < 2; ++mi) {
                    float* c = acc + mi*16 + ni*4;
                    mma_bf16(c, ah[mi], ph);   // Ah*Wh
                    mma_bf16(c, al[mi], ph);   // Al*Wh
                    mma_bf16(c, ah[mi], pl);   // Ah*Wl
                }
            }
        }
        if (pf) {
            __nv_bfloat16* s = st[(it + 1) & 1];
            *(uint4*)(s + ar*SROW + aq*16) = rA0;
            *(uint4*)(s + ar*SROW + aq*16 + 8) = rA1;
            *(uint4*)(s + A_LO_OFF + ar*SROW + aq*16) = rL0;
            *(uint4*)(s + A_LO_OFF + ar*SROW + aq*16 + 8) = rL1;
            uint32_t h0,h1,h2,h3,l0,l1,l2,l3;
            dq2((uint32_t)rW.x, rS, lut, h0, l0);
            dq2((uint32_t)rW.y, rS, lut, h1, l1);
            dq2((uint32_t)rW.z, rS, lut, h2, l2);
            dq2((uint32_t)rW.w, rS, lut, h3, l3);
            *(uint4*)(s + W_HI_OFF + wn*SROW + wc*8) = make_uint4(h0,h1,h2,h3);
            *(uint4*)(s + W_LO_OFF + wn*SROW + wc*8) = make_uint4(l0,l1,l2,l3);
            __syncthreads();
        }
    }

    if (mode == 1) {
#pragma unroll
        for (int mi = 0; mi < 2; ++mi)
#pragma unroll
            for (int ni = 0; ni < 4; ++ni) {
                const float* c = acc + mi*16 + ni*4;
                int r0 = m0 + wm*32 + mi*16 + g;
                int j = n0 + wnw*32 + ni*8 + 2*tt;
                {
                    float t0 = silu_f(gatebuf[(size_t)r0*ldN + j])     * c[0];
                    float t1 = silu_f(gatebuf[(size_t)r0*ldN + j + 1]) * c[1];
                    __nv_bfloat16 h0 = __float2bfloat16(t0), h1 = __float2bfloat16(t1);
                    *(uint32_t*)(t_hi + (size_t)r0*ldN + j) = pack_bf2(h0, h1);
                    *(uint32_t*)(t_lo + (size_t)r0*ldN + j) =
                        pack_bf2(__float2bfloat16(t0 - __bfloat162float(h0)),
                                 __float2bfloat16(t1 - __bfloat162float(h1)));
                }
                {
                    int r1 = r0 + 8;
                    float t2 = silu_f(gatebuf[(size_t)r1*ldN + j])     * c[2];
                    float t3 = silu_f(gatebuf[(size_t)r1*ldN + j + 1]) * c[3];
                    __nv_bfloat16 h2 = __float2bfloat16(t2), h3 = __float2bfloat16(t3);
                    *(uint32_t*)(t_hi + (size_t)r1*ldN + j) = pack_bf2(h2, h3);
                    *(uint32_t*)(t_lo + (size_t)r1*ldN + j) =
                        pack_bf2(__float2bfloat16(t2 - __bfloat162float(h2)),
                                 __float2bfloat16(t3 - __bfloat162float(h3)));
                }
            }
    } else {
        float* po = out + (size_t)blockIdx.z * BATCH * ldN;
#pragma unroll
        for (int mi = 0; mi < 2; ++mi)
#pragma unroll
            for (int ni = 0; ni < 4; ++ni) {
                const float* c = acc + mi*16 + ni*4;
                int r0 = m0 + wm*32 + mi*16 + g;
                int j = n0 + wnw*32 + ni*8 + 2*tt;
                *(float2*)(po + (size_t)r0*ldN + j)     = make_float2(c[0], c[1]);
                *(float2*)(po + (size_t)(r0+8)*ldN + j) = make_float2(c[2], c[3]);
            }
    }
}

__global__ void split_x_kernel(const float* __restrict__ x) {
    int i = blockIdx.x * 256 + threadIdx.x;
    float v = x[i];
    __nv_bfloat16 h = __float2bfloat16(v);
    g_a_hi[i] = h;
    g_a_lo[i] = __float2bfloat16(v - __bfloat162float(h));
}

__global__ void reduce_split_kernel(float* __restrict__ out, int final_layer) {
    int i = blockIdx.x * 256 + threadIdx.x;
    float s = g_part[i] + g_part[i + NELEM_A] + g_part[i + 2*NELEM_A] + g_part[i + 3*NELEM_A];
    if (final_layer) {
        out[i] = s;
    } else {
        __nv_bfloat16 h = __float2bfloat16(s);
        g_a_hi[i] = h;
        g_a_lo[i] = __float2bfloat16(s - __bfloat162float(h));
    }
}

extern "C" void kernel_launch(void* const* d_in, const int* in_sizes, int n_in,
                              void* d_out, int out_size) {
    const float* x  = (const float*)d_in[0];
    const int*   gp = (const int*)d_in[1];
    const float* gs = (const float*)d_in[2];
    const int*   up = (const int*)d_in[3];
    const float* us = (const float*)d_in[4];
    const int*   dp = (const int*)d_in[5];
    const float* ds = (const float*)d_in[6];
    float* out = (float*)d_out;

    cudaFuncSetAttribute(gemm_kernel, cudaFuncAttributeMaxDynamicSharedMemorySize, GEMM_SMEM);

    void *p_ah, *p_al, *p_th, *p_tl, *p_g, *p_part;
    cudaGetSymbolAddress(&p_ah, g_a_hi);
    cudaGetSymbolAddress(&p_al, g_a_lo);
    cudaGetSymbolAddress(&p_th, g_t_hi);
    cudaGetSymbolAddress(&p_tl, g_t_lo);
    cudaGetSymbolAddress(&p_g, g_gate);
    cudaGetSymbolAddress(&p_part, g_part);

    split_x_kernel<<<NELEM_A/256, 256>>>(x);

    for (int l = 0; l < 18; ++l) {
        const size_t woff  = (size_t)l * MLP * (HID/2);
        const size_t soff  = (size_t)l * MLP * (HID/32);
        const size_t dwoff = (size_t)l * HID * (MLP/2);
        const size_t dsoff = (size_t)l * HID * (MLP/32);

        // gate -> g_gate (fp32)
        gemm_kernel<<<dim3(MLP/64, 2, 1), 256, GEMM_SMEM>>>(
            gp + woff, gs + soff,
            (const __nv_bfloat16*)p_ah, (const __nv_bfloat16*)p_al,
            (float*)p_g, HID, MLP, 0, nullptr, nullptr, nullptr);
        // up, fused silu(gate)*up -> t_hi/t_lo
        gemm_kernel<<<dim3(MLP/64, 2, 1), 256, GEMM_SMEM>>>(
            up + woff, us + soff,
            (const __nv_bfloat16*)p_ah, (const __nv_bfloat16*)p_al,
            nullptr, HID, MLP, 1, (const float*)p_g,
            (__nv_bfloat16*)p_th, (__nv_bfloat16*)p_tl);
        // down, split-K 4 -> partials
        gemm_kernel<<<dim3(HID/64, 2, 4), 256, GEMM_SMEM>>>(
            dp + dwoff, ds + dsoff,
            (const __nv_bfloat16*)p_th, (const __nv_bfloat16*)p_tl,
            (float*)p_part, MLP, HID, 0, nullptr, nullptr, nullptr);
        reduce_split_kernel<<<NELEM_A/256, 256>>>(out, l == 17 ? 1 : 0);
    }
}